// round 2
// baseline (speedup 1.0000x reference)
#include <cuda_runtime.h>
#include <cuda_bf16.h>
#include <cstdint>

#define NN_MAX 100000
#define EE_MAX 1600000

// ---------------- device scratch (no allocs allowed) ----------------
__device__ __align__(16) int   g_deg[NN_MAX];
__device__ __align__(16) int   g_cursor[NN_MAX];
__device__ __align__(16) float g_dinv[NN_MAX];
__device__ __align__(16) int   g_off[NN_MAX + 1];
__device__ __align__(16) int   g_offpart[NN_MAX];
__device__ __align__(16) int   g_bsums[128];
__device__ __align__(16) int   g_bsums2[128];
__device__ __align__(16) int   g_srcs[EE_MAX];
__device__ __align__(16) float g_w[EE_MAX];
__device__ __align__(16) float g_h[(size_t)NN_MAX * 128];
__device__ __align__(16) float g_agg[(size_t)NN_MAX * 128];
__device__ int g_is64;

// ---------------- buffer selectors (avoid cudaGetSymbolAddress) -------------
__device__ __forceinline__ const float* sel_in(const float* ext, int sel) {
    return sel == 0 ? ext : (sel == 1 ? (const float*)g_h : (const float*)g_agg);
}
__device__ __forceinline__ float* sel_out(int sel) {
    return sel == 1 ? g_h : g_agg;
}

// ---------------- edge dtype detection (int64 vs int32) ----------------
// int64 little-endian values < 2^31 have zero high words at all odd 32-bit
// positions. int32 data has random node ids there -> P(32 zeros) ~ 0.
__global__ void k_detect(const int* __restrict__ ei32) {
    if (threadIdx.x == 0 && blockIdx.x == 0) {
        int is64 = 1;
        #pragma unroll
        for (int k = 1; k < 64; k += 2)
            if (ei32[k] != 0) { is64 = 0; break; }
        g_is64 = is64;
    }
}

__device__ __forceinline__ int edge_at(const void* __restrict__ ei, long long i) {
    if (g_is64) return (int)((const long long*)ei)[i];
    return ((const int*)ei)[i];
}

// ---------------- degree / normalization ----------------
__global__ void k_init(int n) {
    int i = blockIdx.x * blockDim.x + threadIdx.x;
    if (i < n) { g_deg[i] = 1; g_cursor[i] = 0; }   // self-loop counts 1
}

__global__ void k_count(const void* __restrict__ ei, int E, int n) {
    int e = blockIdx.x * blockDim.x + threadIdx.x;
    if (e >= E) return;
    int d = edge_at(ei, (long long)E + e);
    if ((unsigned)d < (unsigned)n) atomicAdd(&g_deg[d], 1);
}

__global__ void k_dinv(int n) {
    int i = blockIdx.x * blockDim.x + threadIdx.x;
    if (i < n) g_dinv[i] = rsqrtf((float)g_deg[i]);
}

// ---------------- exclusive scan of edge counts (deg-1) ----------------
__global__ void k_scan1(int n) {
    __shared__ int sh[1024];
    int t = threadIdx.x;
    int i = blockIdx.x * 1024 + t;
    int c = (i < n) ? (g_deg[i] - 1) : 0;
    sh[t] = c;
    __syncthreads();
    for (int ofs = 1; ofs < 1024; ofs <<= 1) {
        int v = (t >= ofs) ? sh[t - ofs] : 0;
        __syncthreads();
        sh[t] += v;
        __syncthreads();
    }
    if (i < n) g_offpart[i] = sh[t] - c;          // exclusive within block
    if (t == 1023) g_bsums[blockIdx.x] = sh[1023];
}

__global__ void k_scan2(int nb) {
    __shared__ int sh[128];
    int t = threadIdx.x;
    int c = (t < nb) ? g_bsums[t] : 0;
    sh[t] = c;
    __syncthreads();
    for (int ofs = 1; ofs < 128; ofs <<= 1) {
        int v = (t >= ofs) ? sh[t - ofs] : 0;
        __syncthreads();
        sh[t] += v;
        __syncthreads();
    }
    g_bsums2[t] = sh[t] - c;                      // exclusive block offsets
}

__global__ void k_scan3(int n, int E) {
    int i = blockIdx.x * blockDim.x + threadIdx.x;
    if (i < n) g_off[i] = g_offpart[i] + g_bsums2[i >> 10];
    if (i == 0) g_off[n] = E;
}

// ---------------- counting-sort edges by destination ----------------
__global__ void k_sort(const void* __restrict__ ei, int E, int n) {
    int e = blockIdx.x * blockDim.x + threadIdx.x;
    if (e >= E) return;
    int s = edge_at(ei, e);
    int d = edge_at(ei, (long long)E + e);
    if ((unsigned)s >= (unsigned)n || (unsigned)d >= (unsigned)n) return;
    int pos = g_off[d] + atomicAdd(&g_cursor[d], 1);
    if ((unsigned)pos < (unsigned)EE_MAX) {
        g_srcs[pos] = s;
        g_w[pos] = g_dinv[s] * g_dinv[d];
    }
}

// ---------------- SGEMM: C[M,128] = A[M,128] @ B[128,128] ----------------
// block = 16x16 threads, 128x128 C tile, 8x8 per thread, k-chunks of 16
__global__ void k_gemm128(const float* __restrict__ Aext, int asel, int csel,
                          const float* __restrict__ B, int M) {
    __shared__ __align__(16) float As[128][20];   // 80B row stride: 16B aligned
    __shared__ __align__(16) float Bs[16][128];

    const float* A = sel_in(Aext, asel);
    float* C = sel_out(csel);

    int tx = threadIdx.x, ty = threadIdx.y;
    int tid = ty * 16 + tx;
    int rowBase = blockIdx.x * 128;

    float acc[8][8];
    #pragma unroll
    for (int i = 0; i < 8; i++)
        #pragma unroll
        for (int j = 0; j < 8; j++) acc[i][j] = 0.f;

    for (int k0 = 0; k0 < 128; k0 += 16) {
        #pragma unroll
        for (int l = 0; l < 2; l++) {
            int idx = tid + l * 256;
            int r = idx >> 2;
            int kk4 = (idx & 3) * 4;
            float4 v = make_float4(0.f, 0.f, 0.f, 0.f);
            int gr = rowBase + r;
            if (gr < M)
                v = *reinterpret_cast<const float4*>(&A[(size_t)gr * 128 + k0 + kk4]);
            *reinterpret_cast<float4*>(&As[r][kk4]) = v;
        }
        #pragma unroll
        for (int l = 0; l < 2; l++) {
            int idx = tid + l * 256;
            int kk = idx >> 5;
            int c4 = (idx & 31) * 4;
            *reinterpret_cast<float4*>(&Bs[kk][c4]) =
                *reinterpret_cast<const float4*>(&B[(size_t)(k0 + kk) * 128 + c4]);
        }
        __syncthreads();

        #pragma unroll
        for (int kk = 0; kk < 16; kk++) {
            float a[8], b[8];
            #pragma unroll
            for (int i = 0; i < 8; i++) a[i] = As[ty * 8 + i][kk];
            float4 b0 = *reinterpret_cast<float4*>(&Bs[kk][tx * 8]);
            float4 b1 = *reinterpret_cast<float4*>(&Bs[kk][tx * 8 + 4]);
            b[0] = b0.x; b[1] = b0.y; b[2] = b0.z; b[3] = b0.w;
            b[4] = b1.x; b[5] = b1.y; b[6] = b1.z; b[7] = b1.w;
            #pragma unroll
            for (int i = 0; i < 8; i++)
                #pragma unroll
                for (int j = 0; j < 8; j++)
                    acc[i][j] = fmaf(a[i], b[j], acc[i][j]);
        }
        __syncthreads();
    }

    #pragma unroll
    for (int i = 0; i < 8; i++) {
        int gr = rowBase + ty * 8 + i;
        if (gr < M) {
            #pragma unroll
            for (int j4 = 0; j4 < 8; j4 += 4) {
                float4 v = make_float4(acc[i][j4], acc[i][j4 + 1],
                                       acc[i][j4 + 2], acc[i][j4 + 3]);
                *reinterpret_cast<float4*>(&C[(size_t)gr * 128 + tx * 8 + j4]) = v;
            }
        }
    }
}

// ---------------- aggregation F=128: warp per node, lane owns float4 --------
// out[d] = relu( sum_e h[s_e]*w_e + h[d]*dinv[d]^2 + bias )
__global__ void k_agg128(const float* __restrict__ bias, int hsel, int osel, int n) {
    int node = (blockIdx.x * blockDim.x + threadIdx.x) >> 5;
    int lane = threadIdx.x & 31;
    if (node >= n) return;

    const float4* h4 = reinterpret_cast<const float4*>(sel_in(nullptr, hsel));
    float4* o4 = reinterpret_cast<float4*>(sel_out(osel));

    float dv = g_dinv[node];
    float sw = dv * dv;
    float4 acc = h4[(size_t)node * 32 + lane];
    acc.x *= sw; acc.y *= sw; acc.z *= sw; acc.w *= sw;

    int e0 = g_off[node];
    int e1 = g_off[node + 1];
    for (int e = e0; e < e1; e++) {
        int s = g_srcs[e];          // broadcast across warp
        float we = g_w[e];
        float4 v = h4[(size_t)s * 32 + lane];  // coalesced 512B row read
        acc.x = fmaf(v.x, we, acc.x);
        acc.y = fmaf(v.y, we, acc.y);
        acc.z = fmaf(v.z, we, acc.z);
        acc.w = fmaf(v.w, we, acc.w);
    }
    float4 b = reinterpret_cast<const float4*>(bias)[lane];
    acc.x = fmaxf(acc.x + b.x, 0.f);
    acc.y = fmaxf(acc.y + b.y, 0.f);
    acc.z = fmaxf(acc.z + b.z, 0.f);
    acc.w = fmaxf(acc.w + b.w, 0.f);
    o4[(size_t)node * 32 + lane] = acc;
}

// ---------------- GEMM: g_h[M,8] = g_agg[M,128] @ W[128,8] ----------------
__global__ void k_gemm_n8(const float* __restrict__ W, int M) {
    __shared__ float Ws[128 * 8];
    for (int i = threadIdx.x; i < 1024; i += blockDim.x) Ws[i] = W[i];
    __syncthreads();

    int t = blockIdx.x * blockDim.x + threadIdx.x;
    int row = t >> 3;
    int col = t & 7;
    if (row >= M) return;

    const float4* A4 = reinterpret_cast<const float4*>(g_agg + (size_t)row * 128);
    float acc = 0.f;
    #pragma unroll
    for (int k4 = 0; k4 < 32; k4++) {
        float4 a = A4[k4];
        int kb = k4 * 4;
        acc = fmaf(a.x, Ws[(kb + 0) * 8 + col], acc);
        acc = fmaf(a.y, Ws[(kb + 1) * 8 + col], acc);
        acc = fmaf(a.z, Ws[(kb + 2) * 8 + col], acc);
        acc = fmaf(a.w, Ws[(kb + 3) * 8 + col], acc);
    }
    g_h[(size_t)row * 8 + col] = acc;
}

// ---------------- aggregation F=8: g_agg[M,8] = agg(g_h[M,8]) ---------------
__global__ void k_agg8(const float* __restrict__ bias, int n) {
    int t = blockIdx.x * blockDim.x + threadIdx.x;
    int node = t >> 3;
    int f = t & 7;
    if (node >= n) return;

    float dv = g_dinv[node];
    float acc = g_h[(size_t)node * 8 + f] * dv * dv;
    int e0 = g_off[node];
    int e1 = g_off[node + 1];
    for (int e = e0; e < e1; e++) {
        int s = g_srcs[e];
        acc = fmaf(g_h[(size_t)s * 8 + f], g_w[e], acc);
    }
    acc = fmaxf(acc + bias[f], 0.f);
    g_agg[(size_t)node * 8 + f] = acc;
}

// ---------------- classifier: out[M,16] = g_agg[M,8] @ Wc[8,16] + bc --------
__global__ void k_cls(const float* __restrict__ Wc,
                      const float* __restrict__ bc,
                      float* __restrict__ out, int M) {
    __shared__ float Ws[8 * 16];
    __shared__ float bs[16];
    if (threadIdx.x < 128) Ws[threadIdx.x] = Wc[threadIdx.x];
    if (threadIdx.x < 16) bs[threadIdx.x] = bc[threadIdx.x];
    __syncthreads();

    int t = blockIdx.x * blockDim.x + threadIdx.x;
    int row = t >> 4;
    int col = t & 15;
    if (row >= M) return;

    const float4* A4 = reinterpret_cast<const float4*>(g_agg + (size_t)row * 8);
    float4 a0 = A4[0];
    float4 a1 = A4[1];
    float acc = bs[col];
    acc = fmaf(a0.x, Ws[0 * 16 + col], acc);
    acc = fmaf(a0.y, Ws[1 * 16 + col], acc);
    acc = fmaf(a0.z, Ws[2 * 16 + col], acc);
    acc = fmaf(a0.w, Ws[3 * 16 + col], acc);
    acc = fmaf(a1.x, Ws[4 * 16 + col], acc);
    acc = fmaf(a1.y, Ws[5 * 16 + col], acc);
    acc = fmaf(a1.z, Ws[6 * 16 + col], acc);
    acc = fmaf(a1.w, Ws[7 * 16 + col], acc);
    out[(size_t)row * 16 + col] = acc;
}

// ---------------- launch ----------------
extern "C" void kernel_launch(void* const* d_in, const int* in_sizes, int n_in,
                              void* d_out, int out_size) {
    const float* x  = (const float*)d_in[0];
    const void*  ei = d_in[1];
    const float* W1 = (const float*)d_in[2];
    const float* b1 = (const float*)d_in[3];
    const float* W2 = (const float*)d_in[4];
    const float* b2 = (const float*)d_in[5];
    const float* W3 = (const float*)d_in[6];
    const float* b3 = (const float*)d_in[7];
    const float* Wc = (const float*)d_in[8];
    const float* bc = (const float*)d_in[9];
    float* out = (float*)d_out;

    int n = in_sizes[0] / 128;
    int E = in_sizes[1] / 2;

    // graph structure (degree, norm, dst-sorted edge list)
    k_detect<<<1, 32>>>((const int*)ei);
    k_init<<<(n + 255) / 256, 256>>>(n);
    k_count<<<(E + 255) / 256, 256>>>(ei, E, n);
    k_dinv<<<(n + 255) / 256, 256>>>(n);
    int nb = (n + 1023) / 1024;
    k_scan1<<<nb, 1024>>>(n);
    k_scan2<<<1, 128>>>(nb);
    k_scan3<<<(n + 255) / 256, 256>>>(n, E);
    k_sort<<<(E + 255) / 256, 256>>>(ei, E, n);

    dim3 gblk(16, 16);
    int gemmGrid = (n + 127) / 128;
    int aggGrid128 = (int)(((long long)n * 32 + 255) / 256);

    // layer 1: h = x@W1 ; agg -> g_agg
    k_gemm128<<<gemmGrid, gblk>>>(x, 0, 1, W1, n);
    k_agg128<<<aggGrid128, 256>>>(b1, 1, 2, n);
    // layer 2: h = g_agg@W2 ; agg -> g_agg ... ping-pong via g_h
    k_gemm128<<<gemmGrid, gblk>>>(nullptr, 2, 1, W2, n);
    k_agg128<<<aggGrid128, 256>>>(b2, 1, 2, n);
    // layer 3 (F=8): g_h = g_agg@W3 ; agg8 -> g_agg
    k_gemm_n8<<<(int)(((long long)n * 8 + 255) / 256), 256>>>(W3, n);
    k_agg8<<<(int)(((long long)n * 8 + 255) / 256), 256>>>(b3, n);
    // classifier
    k_cls<<<(int)(((long long)n * 16 + 255) / 256), 256>>>(Wc, bc, out, n);
}

// round 3
// speedup vs baseline: 1.0675x; 1.0675x over previous
#include <cuda_runtime.h>
#include <cuda_bf16.h>
#include <cstdint>

#define NN_MAX 100000
#define EE_MAX 1600000

// ---------------- device scratch (no allocs allowed) ----------------
__device__ __align__(16) int   g_deg[NN_MAX];
__device__ __align__(16) int   g_cursor[NN_MAX];
__device__ __align__(16) float g_dinv[NN_MAX];
__device__ __align__(16) int   g_off[NN_MAX + 1];
__device__ __align__(16) int   g_offpart[NN_MAX];
__device__ __align__(16) int   g_bsums[128];
__device__ __align__(16) int   g_bsums2[128];
__device__ __align__(16) int   g_srcs[EE_MAX];
__device__ __align__(16) float g_w[EE_MAX];
__device__ __align__(16) float g_h[(size_t)NN_MAX * 128];
__device__ __align__(16) float g_agg[(size_t)NN_MAX * 128];
__device__ int g_is64;

// ---------------- packed f32x2 helpers (FFMA2: 2x FFMA throughput) ---------
__device__ __forceinline__ void fma2(unsigned long long& d,
                                     unsigned long long a,
                                     unsigned long long b) {
    asm("fma.rn.f32x2 %0, %1, %2, %0;" : "+l"(d) : "l"(a), "l"(b));
}
__device__ __forceinline__ unsigned long long pack2(float lo, float hi) {
    unsigned long long r;
    asm("mov.b64 %0, {%1, %2};" : "=l"(r) : "f"(lo), "f"(hi));
    return r;
}
__device__ __forceinline__ float2 unpack2(unsigned long long v) {
    float lo, hi;
    asm("mov.b64 {%0, %1}, %2;" : "=f"(lo), "=f"(hi) : "l"(v));
    return make_float2(lo, hi);
}

// ---------------- buffer selectors (avoid cudaGetSymbolAddress) -------------
__device__ __forceinline__ const float* sel_in(const float* ext, int sel) {
    return sel == 0 ? ext : (sel == 1 ? (const float*)g_h : (const float*)g_agg);
}
__device__ __forceinline__ float* sel_out(int sel) {
    return sel == 1 ? g_h : g_agg;
}

// ---------------- edge dtype detection (int64 vs int32) ----------------
__global__ void k_detect(const int* __restrict__ ei32) {
    if (threadIdx.x == 0 && blockIdx.x == 0) {
        int is64 = 1;
        #pragma unroll
        for (int k = 1; k < 64; k += 2)
            if (ei32[k] != 0) { is64 = 0; break; }
        g_is64 = is64;
    }
}

__device__ __forceinline__ int edge_at(const void* __restrict__ ei, long long i) {
    if (g_is64) return (int)((const long long*)ei)[i];
    return ((const int*)ei)[i];
}

// ---------------- degree / normalization ----------------
__global__ void k_init(int n) {
    int i = blockIdx.x * blockDim.x + threadIdx.x;
    if (i < n) { g_deg[i] = 1; g_cursor[i] = 0; }   // self-loop counts 1
}

__global__ void k_count(const void* __restrict__ ei, int E, int n) {
    int e = blockIdx.x * blockDim.x + threadIdx.x;
    if (e >= E) return;
    int d = edge_at(ei, (long long)E + e);
    if ((unsigned)d < (unsigned)n) atomicAdd(&g_deg[d], 1);
}

// ---------------- exclusive scan of edge counts (deg-1) ----------------
__global__ void k_scan1(int n) {
    __shared__ int sh[1024];
    int t = threadIdx.x;
    int i = blockIdx.x * 1024 + t;
    int c = (i < n) ? (g_deg[i] - 1) : 0;
    sh[t] = c;
    __syncthreads();
    for (int ofs = 1; ofs < 1024; ofs <<= 1) {
        int v = (t >= ofs) ? sh[t - ofs] : 0;
        __syncthreads();
        sh[t] += v;
        __syncthreads();
    }
    if (i < n) g_offpart[i] = sh[t] - c;          // exclusive within block
    if (t == 1023) g_bsums[blockIdx.x] = sh[1023];
}

__global__ void k_scan2(int nb) {
    __shared__ int sh[128];
    int t = threadIdx.x;
    int c = (t < nb) ? g_bsums[t] : 0;
    sh[t] = c;
    __syncthreads();
    for (int ofs = 1; ofs < 128; ofs <<= 1) {
        int v = (t >= ofs) ? sh[t - ofs] : 0;
        __syncthreads();
        sh[t] += v;
        __syncthreads();
    }
    g_bsums2[t] = sh[t] - c;                      // exclusive block offsets
}

__global__ void k_scan3(int n, int E) {
    int i = blockIdx.x * blockDim.x + threadIdx.x;
    if (i < n) {
        g_off[i] = g_offpart[i] + g_bsums2[i >> 10];
        g_dinv[i] = rsqrtf((float)g_deg[i]);      // fused dinv
    }
    if (i == 0) g_off[n] = E;
}

// ---------------- counting-sort edges by destination ----------------
__global__ void k_sort(const void* __restrict__ ei, int E, int n) {
    int e = blockIdx.x * blockDim.x + threadIdx.x;
    if (e >= E) return;
    int s = edge_at(ei, e);
    int d = edge_at(ei, (long long)E + e);
    if ((unsigned)s >= (unsigned)n || (unsigned)d >= (unsigned)n) return;
    int pos = g_off[d] + atomicAdd(&g_cursor[d], 1);
    if ((unsigned)pos < (unsigned)EE_MAX) {
        g_srcs[pos] = s;
        g_w[pos] = g_dinv[s] * g_dinv[d];
    }
}

// ---------------- SGEMM: C[M,128] = A[M,128] @ B[128,128] ----------------
// 256 threads, 128x128 C tile, 8x8 per thread, k-chunk 16.
// Smem tiles in [k][m]/[k][n] layout -> conflict-free LDS.128 fragment reads.
// Inner product uses packed fma.rn.f32x2 (FFMA2) for 2x FP32 throughput.
__global__ void __launch_bounds__(256, 2)
k_gemm128(const float* __restrict__ Aext, int asel, int csel,
          const float* __restrict__ B, int M) {
    __shared__ __align__(16) float As[16][132];   // 132: 16B-aligned rows, low conflict
    __shared__ __align__(16) float Bs[16][128];

    const float* A = sel_in(Aext, asel);
    float* C = sel_out(csel);

    int tid = threadIdx.x;
    int tx = tid & 15;
    int ty = tid >> 4;
    int rowBase = blockIdx.x * 128;

    // load-index precompute (2 float4 per thread per tile, per matrix)
    int aR[2], aK[2], bK[2], bC[2];
    #pragma unroll
    for (int l = 0; l < 2; l++) {
        int idx = tid + l * 256;
        aR[l] = idx >> 2;            // 0..127 (row within tile)
        aK[l] = (idx & 3) * 4;       // 0,4,8,12 (k within chunk)
        bK[l] = idx >> 5;            // 0..15
        bC[l] = (idx & 31) * 4;      // 0..124
    }

    unsigned long long acc[8][4];
    #pragma unroll
    for (int i = 0; i < 8; i++)
        #pragma unroll
        for (int j = 0; j < 4; j++) acc[i][j] = 0ull;

    // prefetch chunk 0
    float4 ra[2], rb[2];
    #pragma unroll
    for (int l = 0; l < 2; l++) {
        int gr = rowBase + aR[l];
        ra[l] = (gr < M)
            ? *reinterpret_cast<const float4*>(&A[(size_t)gr * 128 + aK[l]])
            : make_float4(0.f, 0.f, 0.f, 0.f);
        rb[l] = *reinterpret_cast<const float4*>(&B[(size_t)bK[l] * 128 + bC[l]]);
    }

    for (int k0 = 0; k0 < 128; k0 += 16) {
        // regs -> smem (A transposed to [k][m])
        #pragma unroll
        for (int l = 0; l < 2; l++) {
            As[aK[l] + 0][aR[l]] = ra[l].x;
            As[aK[l] + 1][aR[l]] = ra[l].y;
            As[aK[l] + 2][aR[l]] = ra[l].z;
            As[aK[l] + 3][aR[l]] = ra[l].w;
            *reinterpret_cast<float4*>(&Bs[bK[l]][bC[l]]) = rb[l];
        }
        __syncthreads();

        // prefetch next chunk while computing this one
        if (k0 < 112) {
            int kn = k0 + 16;
            #pragma unroll
            for (int l = 0; l < 2; l++) {
                int gr = rowBase + aR[l];
                ra[l] = (gr < M)
                    ? *reinterpret_cast<const float4*>(&A[(size_t)gr * 128 + kn + aK[l]])
                    : make_float4(0.f, 0.f, 0.f, 0.f);
                rb[l] = *reinterpret_cast<const float4*>(&B[(size_t)(kn + bK[l]) * 128 + bC[l]]);
            }
        }

        #pragma unroll
        for (int kk = 0; kk < 16; kk++) {
            float4 a0 = *reinterpret_cast<float4*>(&As[kk][ty * 8]);
            float4 a1 = *reinterpret_cast<float4*>(&As[kk][ty * 8 + 4]);
            float4 b0 = *reinterpret_cast<float4*>(&Bs[kk][tx * 8]);
            float4 b1 = *reinterpret_cast<float4*>(&Bs[kk][tx * 8 + 4]);
            unsigned long long bb[4];
            bb[0] = pack2(b0.x, b0.y);
            bb[1] = pack2(b0.z, b0.w);
            bb[2] = pack2(b1.x, b1.y);
            bb[3] = pack2(b1.z, b1.w);
            float av[8] = {a0.x, a0.y, a0.z, a0.w, a1.x, a1.y, a1.z, a1.w};
            #pragma unroll
            for (int i = 0; i < 8; i++) {
                unsigned long long aa = pack2(av[i], av[i]);
                fma2(acc[i][0], aa, bb[0]);
                fma2(acc[i][1], aa, bb[1]);
                fma2(acc[i][2], aa, bb[2]);
                fma2(acc[i][3], aa, bb[3]);
            }
        }
        __syncthreads();
    }

    #pragma unroll
    for (int i = 0; i < 8; i++) {
        int gr = rowBase + ty * 8 + i;
        if (gr < M) {
            float2 v0 = unpack2(acc[i][0]);
            float2 v1 = unpack2(acc[i][1]);
            float2 v2 = unpack2(acc[i][2]);
            float2 v3 = unpack2(acc[i][3]);
            float4 o0 = make_float4(v0.x, v0.y, v1.x, v1.y);
            float4 o1 = make_float4(v2.x, v2.y, v3.x, v3.y);
            *reinterpret_cast<float4*>(&C[(size_t)gr * 128 + tx * 8]) = o0;
            *reinterpret_cast<float4*>(&C[(size_t)gr * 128 + tx * 8 + 4]) = o1;
        }
    }
}

// ---------------- aggregation F=128: warp per node, lane owns float4 --------
// out[d] = relu( sum_e h[s_e]*w_e + h[d]*dinv[d]^2 + bias )
__global__ void k_agg128(const float* __restrict__ bias, int hsel, int osel, int n) {
    int node = (blockIdx.x * blockDim.x + threadIdx.x) >> 5;
    int lane = threadIdx.x & 31;
    if (node >= n) return;

    const float4* h4 = reinterpret_cast<const float4*>(sel_in(nullptr, hsel));
    float4* o4 = reinterpret_cast<float4*>(sel_out(osel));

    float dv = g_dinv[node];
    float sw = dv * dv;
    float4 acc = h4[(size_t)node * 32 + lane];
    acc.x *= sw; acc.y *= sw; acc.z *= sw; acc.w *= sw;

    int e0 = g_off[node];
    int e1 = g_off[node + 1];
    for (int e = e0; e < e1; e++) {
        int s = g_srcs[e];          // broadcast across warp
        float we = g_w[e];
        float4 v = h4[(size_t)s * 32 + lane];  // coalesced 512B row read
        acc.x = fmaf(v.x, we, acc.x);
        acc.y = fmaf(v.y, we, acc.y);
        acc.z = fmaf(v.z, we, acc.z);
        acc.w = fmaf(v.w, we, acc.w);
    }
    float4 b = reinterpret_cast<const float4*>(bias)[lane];
    acc.x = fmaxf(acc.x + b.x, 0.f);
    acc.y = fmaxf(acc.y + b.y, 0.f);
    acc.z = fmaxf(acc.z + b.z, 0.f);
    acc.w = fmaxf(acc.w + b.w, 0.f);
    o4[(size_t)node * 32 + lane] = acc;
}

// ---------------- GEMM: g_h[M,8] = g_agg[M,128] @ W[128,8] ----------------
__global__ void k_gemm_n8(const float* __restrict__ W, int M) {
    __shared__ float Ws[128 * 8];
    for (int i = threadIdx.x; i < 1024; i += blockDim.x) Ws[i] = W[i];
    __syncthreads();

    int t = blockIdx.x * blockDim.x + threadIdx.x;
    int row = t >> 3;
    int col = t & 7;
    if (row >= M) return;

    const float4* A4 = reinterpret_cast<const float4*>(g_agg + (size_t)row * 128);
    float acc = 0.f;
    #pragma unroll
    for (int k4 = 0; k4 < 32; k4++) {
        float4 a = A4[k4];
        int kb = k4 * 4;
        acc = fmaf(a.x, Ws[(kb + 0) * 8 + col], acc);
        acc = fmaf(a.y, Ws[(kb + 1) * 8 + col], acc);
        acc = fmaf(a.z, Ws[(kb + 2) * 8 + col], acc);
        acc = fmaf(a.w, Ws[(kb + 3) * 8 + col], acc);
    }
    g_h[(size_t)row * 8 + col] = acc;
}

// ---------------- aggregation F=8: g_agg[M,8] = agg(g_h[M,8]) ---------------
__global__ void k_agg8(const float* __restrict__ bias, int n) {
    int t = blockIdx.x * blockDim.x + threadIdx.x;
    int node = t >> 3;
    int f = t & 7;
    if (node >= n) return;

    float dv = g_dinv[node];
    float acc = g_h[(size_t)node * 8 + f] * dv * dv;
    int e0 = g_off[node];
    int e1 = g_off[node + 1];
    for (int e = e0; e < e1; e++) {
        int s = g_srcs[e];
        acc = fmaf(g_h[(size_t)s * 8 + f], g_w[e], acc);
    }
    acc = fmaxf(acc + bias[f], 0.f);
    g_agg[(size_t)node * 8 + f] = acc;
}

// ---------------- classifier: out[M,16] = g_agg[M,8] @ Wc[8,16] + bc --------
__global__ void k_cls(const float* __restrict__ Wc,
                      const float* __restrict__ bc,
                      float* __restrict__ out, int M) {
    __shared__ float Ws[8 * 16];
    __shared__ float bs[16];
    if (threadIdx.x < 128) Ws[threadIdx.x] = Wc[threadIdx.x];
    if (threadIdx.x < 16) bs[threadIdx.x] = bc[threadIdx.x];
    __syncthreads();

    int t = blockIdx.x * blockDim.x + threadIdx.x;
    int row = t >> 4;
    int col = t & 15;
    if (row >= M) return;

    const float4* A4 = reinterpret_cast<const float4*>(g_agg + (size_t)row * 8);
    float4 a0 = A4[0];
    float4 a1 = A4[1];
    float acc = bs[col];
    acc = fmaf(a0.x, Ws[0 * 16 + col], acc);
    acc = fmaf(a0.y, Ws[1 * 16 + col], acc);
    acc = fmaf(a0.z, Ws[2 * 16 + col], acc);
    acc = fmaf(a0.w, Ws[3 * 16 + col], acc);
    acc = fmaf(a1.x, Ws[4 * 16 + col], acc);
    acc = fmaf(a1.y, Ws[5 * 16 + col], acc);
    acc = fmaf(a1.z, Ws[6 * 16 + col], acc);
    acc = fmaf(a1.w, Ws[7 * 16 + col], acc);
    out[(size_t)row * 16 + col] = acc;
}

// ---------------- launch ----------------
extern "C" void kernel_launch(void* const* d_in, const int* in_sizes, int n_in,
                              void* d_out, int out_size) {
    const float* x  = (const float*)d_in[0];
    const void*  ei = d_in[1];
    const float* W1 = (const float*)d_in[2];
    const float* b1 = (const float*)d_in[3];
    const float* W2 = (const float*)d_in[4];
    const float* b2 = (const float*)d_in[5];
    const float* W3 = (const float*)d_in[6];
    const float* b3 = (const float*)d_in[7];
    const float* Wc = (const float*)d_in[8];
    const float* bc = (const float*)d_in[9];
    float* out = (float*)d_out;

    int n = in_sizes[0] / 128;
    int E = in_sizes[1] / 2;

    // graph structure (degree, norm, dst-sorted edge list)
    k_detect<<<1, 32>>>((const int*)ei);
    k_init<<<(n + 255) / 256, 256>>>(n);
    k_count<<<(E + 255) / 256, 256>>>(ei, E, n);
    int nb = (n + 1023) / 1024;
    k_scan1<<<nb, 1024>>>(n);
    k_scan2<<<1, 128>>>(nb);
    k_scan3<<<(n + 255) / 256, 256>>>(n, E);
    k_sort<<<(E + 255) / 256, 256>>>(ei, E, n);

    int gemmGrid = (n + 127) / 128;
    int aggGrid128 = (int)(((long long)n * 32 + 255) / 256);

    // layer 1: h = x@W1 ; agg -> g_agg
    k_gemm128<<<gemmGrid, 256>>>(x, 0, 1, W1, n);
    k_agg128<<<aggGrid128, 256>>>(b1, 1, 2, n);
    // layer 2: h = g_agg@W2 ; agg -> g_agg ... ping-pong via g_h
    k_gemm128<<<gemmGrid, 256>>>(nullptr, 2, 1, W2, n);
    k_agg128<<<aggGrid128, 256>>>(b2, 1, 2, n);
    // layer 3 (F=8): g_h = g_agg@W3 ; agg8 -> g_agg
    k_gemm_n8<<<(int)(((long long)n * 8 + 255) / 256), 256>>>(W3, n);
    k_agg8<<<(int)(((long long)n * 8 + 255) / 256), 256>>>(b3, n);
    // classifier
    k_cls<<<(int)(((long long)n * 16 + 255) / 256), 256>>>(Wc, bc, out, n);
}